// round 13
// baseline (speedup 1.0000x reference)
#include <cuda_runtime.h>
#include <cuda_fp16.h>
#include <cstdint>

// Shape fixed by setup_inputs: B=1, H=8, N=4096, D=64, fp32 in/out.
#define HEADS 8
#define NSEQ  4096
#define DDIM  64
#define TILE  128
#define KTILES 2            // two 128-col K tiles resident -> 128x256 per CTA

// SW128 swizzle (Swizzle<3,4,3>) on byte offsets relative to a 1024B-aligned base.
#define SW128(off) ((off) ^ ((((uint32_t)(off)) >> 3) & 0x70))

// Pre-scaled norms: g_q2[r] = -0.5*log2(e)*||q_r||^2 (same for k).
__device__ float g_q2[HEADS * NSEQ];
__device__ float g_k2[HEADS * NSEQ];
// fp16 hi/lo split of Q and K, same [h, row, d] layout (4 MB each).
__device__ __half g_qhi[HEADS * NSEQ * DDIM];
__device__ __half g_qlo[HEADS * NSEQ * DDIM];
__device__ __half g_khi[HEADS * NSEQ * DDIM];
__device__ __half g_klo[HEADS * NSEQ * DDIM];

// ---------------------------------------------------------------------------
// Kernel 1: fused (pre-scaled) norms + fp16 hi/lo split, single input pass.
// ---------------------------------------------------------------------------
__global__ void hept_prep_kernel(const float* __restrict__ q,
                                 const float* __restrict__ k) {
    const int tid = threadIdx.x;
    const int rloc = tid >> 4;
    const int c4   = tid & 15;
    const int row  = blockIdx.x * 16 + rloc;
    const float* src = (blockIdx.y == 0) ? q : k;
    float*       nrm = (blockIdx.y == 0) ? g_q2 : g_k2;
    __half* hi = (blockIdx.y == 0) ? g_qhi : g_khi;
    __half* lo = (blockIdx.y == 0) ? g_qlo : g_klo;

    float4 v = reinterpret_cast<const float4*>(src)[row * 16 + c4];

    __half2 h01 = __floats2half2_rn(v.x, v.y);
    __half2 h23 = __floats2half2_rn(v.z, v.w);
    float2 f01 = __half22float2(h01);
    float2 f23 = __half22float2(h23);
    __half2 l01 = __floats2half2_rn(v.x - f01.x, v.y - f01.y);
    __half2 l23 = __floats2half2_rn(v.z - f23.x, v.w - f23.y);
    reinterpret_cast<uint2*>(hi)[row * 16 + c4] =
        make_uint2(*reinterpret_cast<uint32_t*>(&h01), *reinterpret_cast<uint32_t*>(&h23));
    reinterpret_cast<uint2*>(lo)[row * 16 + c4] =
        make_uint2(*reinterpret_cast<uint32_t*>(&l01), *reinterpret_cast<uint32_t*>(&l23));

    float s = v.x * v.x + v.y * v.y + v.z * v.z + v.w * v.w;
#pragma unroll
    for (int off = 8; off >= 1; off >>= 1)
        s += __shfl_xor_sync(0xffffffffu, s, off);
    if (c4 == 0) nrm[row] = s * -0.72134752044448170368f;   // -0.5*log2(e)
}

// ---------------------------------------------------------------------------
static __device__ __forceinline__ uint32_t smem_u32(const void* p) {
    uint32_t a;
    asm("{ .reg .u64 t; cvta.to.shared.u64 t, %1; cvt.u32.u64 %0, t; }"
        : "=r"(a) : "l"(p));
    return a;
}

static __device__ __forceinline__ float ex2(float x) {
    float y;
    asm("ex2.approx.f32 %0, %1;" : "=f"(y) : "f"(x));
    return y;
}

#define CP_ASYNC16(dst, src)                                                  \
    asm volatile("cp.async.cg.shared.global [%0], [%1], 16;"                  \
                 :: "r"(dst), "l"(src) : "memory")

#define LDMATRIX_X4(r0, r1, r2, r3, addr)                                     \
    asm volatile("ldmatrix.sync.aligned.m8n8.x4.shared.b16 {%0,%1,%2,%3}, [%4];" \
                 : "=r"(r0), "=r"(r1), "=r"(r2), "=r"(r3) : "r"(addr))

#define MMA_16816(c, a, b)                                                     \
    asm volatile("mma.sync.aligned.m16n8k16.row.col.f32.f16.f16.f32 "         \
                 "{%0,%1,%2,%3}, {%4,%5,%6,%7}, {%8,%9}, {%0,%1,%2,%3};"      \
                 : "+f"((c)[0]), "+f"((c)[1]), "+f"((c)[2]), "+f"((c)[3])     \
                 : "r"((a)[0]), "r"((a)[1]), "r"((a)[2]), "r"((a)[3]),        \
                   "r"((b)[0]), "r"((b)[1]))

// ---------------------------------------------------------------------------
// Kernel 2: HMMA fp16-split GEMM + log2-exp epilogue, software-pipelined:
// each tile's accumulators are split into nt01/nt23 halves; the epilogue of
// a completed half is interleaved (one mt-chunk per ks step) with the MMA
// stream of the next half, keeping the tensor pipe fed.
// Grid (16, 32, 8), 256 threads (8 warps, 2m x 4n), warp tile 64x32.
// dyn smem: QHI|QLO (16KB each) | KHI(32KB) | KLO(32KB) = 96KB, 2 CTAs/SM.
// ---------------------------------------------------------------------------
#define SM_QB   16384
#define SM_KB   32768
#define SM_ALLOC (2 * SM_QB + 2 * SM_KB + 1024)

// One epilogue chunk: rows (wm*64 + mt*16 + lane/4) and +8, 2 nt groups
// starting at column base cgb within the warp's 32 cols of tile column colt.
#define EPI_CHUNK(vv, mt, colt, cgb) do {                                      \
    const int rA = wm * 64 + (mt) * 16 + (lane >> 2);                          \
    const int rB = rA + 8;                                                     \
    const float cqA = q2p[rA];                                                 \
    const float cqB = q2p[rB];                                                 \
    const float* k2p = g_k2 + h * NSEQ + (colt) + wn * 32 + (cgb);             \
    float* orowA = outh + (size_t)(row0 + rA) * NSEQ + (colt) + wn * 32 + (cgb); \
    float* orowB = outh + (size_t)(row0 + rB) * NSEQ + (colt) + wn * 32 + (cgb); \
    _Pragma("unroll")                                                          \
    for (int nt = 0; nt < 2; ++nt) {                                           \
        const int c = nt * 8 + (lane & 3) * 2;                                 \
        const float ckA = k2p[c];                                              \
        const float ckB = k2p[c + 1];                                          \
        const float* v = (vv)[mt][nt];                                         \
        float2 oA, oB;                                                         \
        oA.x = ex2(fminf(fmaf(v[0], L2E, cqA + ckA), 0.f));                    \
        oA.y = ex2(fminf(fmaf(v[1], L2E, cqA + ckB), 0.f));                    \
        oB.x = ex2(fminf(fmaf(v[2], L2E, cqB + ckA), 0.f));                    \
        oB.y = ex2(fminf(fmaf(v[3], L2E, cqB + ckB), 0.f));                    \
        *reinterpret_cast<float2*>(orowA + c) = oA;                            \
        *reinterpret_cast<float2*>(orowB + c) = oB;                            \
    }                                                                          \
} while (0)

__global__ __launch_bounds__(256, 2)
void hept_mma_kernel(float* __restrict__ out) {
    extern __shared__ char smem_raw[];
    const uint32_t sbase = smem_u32(smem_raw);
    const uint32_t abase = (sbase + 1023u) & ~1023u;

    const uint32_t QHI = abase;
    const uint32_t QLO = abase + SM_QB;
    const uint32_t KHI = abase + 2 * SM_QB;
    const uint32_t KLO = abase + 2 * SM_QB + SM_KB;

    const int tid  = threadIdx.x;
    const int lane = tid & 31;
    const int wid  = tid >> 5;
    const int wm   = wid >> 2;          // 0..1 -> 64-row slab
    const int wn   = wid & 3;           // 0..3 -> 32-col slab
    const int h    = blockIdx.z;
    const int row0 = blockIdx.y * TILE;
    const int col0 = blockIdx.x * (TILE * KTILES);

    const __half* qhis = g_qhi + ((size_t)h * NSEQ + row0) * DDIM;
    const __half* qlos = g_qlo + ((size_t)h * NSEQ + row0) * DDIM;
    const __half* khis = g_khi + ((size_t)h * NSEQ + col0) * DDIM;
    const __half* klos = g_klo + ((size_t)h * NSEQ + col0) * DDIM;

    // --- single load phase: Q 128 rows, K 256 rows (hi+lo each), 16B chunks.
#pragma unroll
    for (int it = 0; it < 4; ++it) {
        int idx = tid + it * 256;
        int r   = idx >> 3;
        int c16 = idx & 7;
        uint32_t soff = SW128((uint32_t)(r * 128 + c16 * 16));
        size_t goff = (size_t)r * DDIM + c16 * 8;
        CP_ASYNC16(QHI + soff, qhis + goff);
        CP_ASYNC16(QLO + soff, qlos + goff);
    }
#pragma unroll
    for (int it = 0; it < 8; ++it) {
        int idx = tid + it * 256;
        int r   = idx >> 3;
        int c16 = idx & 7;
        uint32_t soff = SW128((uint32_t)(r * 128 + c16 * 16));
        size_t goff = (size_t)r * DDIM + c16 * 8;
        CP_ASYNC16(KHI + soff, khis + goff);
        CP_ASYNC16(KLO + soff, klos + goff);
    }
    asm volatile("cp.async.commit_group;" ::: "memory");
    asm volatile("cp.async.wait_group 0;" ::: "memory");
    __syncthreads();

    // --- hoisted swizzled LDSM offsets.
    const uint32_t mask = (uint32_t)((lane & 7) << 4);
    const uint32_t a_row = (uint32_t)(wm * 64 + (lane & 7) + ((lane >> 3) & 1) * 8);
    const uint32_t a_colb = (uint32_t)(((lane >> 4) & 1) * 16);
    const uint32_t b_row = (uint32_t)(wn * 32 + (lane & 7) + ((lane >> 4) & 1) * 8);
    const uint32_t b_colb = (uint32_t)(((lane >> 3) & 1) * 16);
    uint32_t aoff[4], boff[4];
#pragma unroll
    for (int ks = 0; ks < 4; ++ks) {
        aoff[ks] = a_row * 128 + ((a_colb + (uint32_t)(ks * 32)) ^ mask);
        boff[ks] = b_row * 128 + ((b_colb + (uint32_t)(ks * 32)) ^ mask);
    }

    const float L2E = 1.4426950408889634f;
    const float* q2p = g_q2 + h * NSEQ + row0;
    float* outh = out + (size_t)h * NSEQ * NSEQ;

    float acc1[4][2][4];    // nt23 half, carried across tile boundary
    int pcolt = 0;          // column base of the tile acc1 belongs to

#pragma unroll
    for (int t = 0; t < KTILES; ++t) {
        const uint32_t KHt = KHI + (uint32_t)t * (TILE * 128);
        const uint32_t KLt = KLO + (uint32_t)t * (TILE * 128);
        const int colt = col0 + t * TILE;

        float acc0[4][2][4];
#pragma unroll
        for (int mt = 0; mt < 4; ++mt)
#pragma unroll
            for (int nt = 0; nt < 2; ++nt)
#pragma unroll
                for (int i = 0; i < 4; ++i) acc0[mt][nt][i] = 0.f;

        // ---- Phase A: MMA nt01; interleave epilogue of previous tile's acc1.
#pragma unroll
        for (int ks = 0; ks < 4; ++ks) {
            uint32_t ahi[4][4], alo[4][4];
#pragma unroll
            for (int mt = 0; mt < 4; ++mt) {
                LDMATRIX_X4(ahi[mt][0], ahi[mt][1], ahi[mt][2], ahi[mt][3],
                            QHI + aoff[ks] + (uint32_t)(mt * 2048));
                LDMATRIX_X4(alo[mt][0], alo[mt][1], alo[mt][2], alo[mt][3],
                            QLO + aoff[ks] + (uint32_t)(mt * 2048));
            }
            uint32_t bhi[2][2], blo[2][2];
            {
                uint32_t r0, r1, r2, r3;
                LDMATRIX_X4(r0, r1, r2, r3, KHt + boff[ks]);
                bhi[0][0] = r0; bhi[0][1] = r1; bhi[1][0] = r2; bhi[1][1] = r3;
                LDMATRIX_X4(r0, r1, r2, r3, KLt + boff[ks]);
                blo[0][0] = r0; blo[0][1] = r1; blo[1][0] = r2; blo[1][1] = r3;
            }
#pragma unroll
            for (int mt = 0; mt < 4; ++mt)
#pragma unroll
                for (int nt = 0; nt < 2; ++nt) {
                    MMA_16816(acc0[mt][nt], ahi[mt], bhi[nt]);
                    MMA_16816(acc0[mt][nt], alo[mt], bhi[nt]);
                    MMA_16816(acc0[mt][nt], ahi[mt], blo[nt]);
                }
            if (t > 0) EPI_CHUNK(acc1, ks, pcolt, 16);
        }

        // ---- Phase B: MMA nt23 into acc1; interleave epilogue of acc0.
#pragma unroll
        for (int mt = 0; mt < 4; ++mt)
#pragma unroll
            for (int nt = 0; nt < 2; ++nt)
#pragma unroll
                for (int i = 0; i < 4; ++i) acc1[mt][nt][i] = 0.f;

#pragma unroll
        for (int ks = 0; ks < 4; ++ks) {
            uint32_t ahi[4][4], alo[4][4];
#pragma unroll
            for (int mt = 0; mt < 4; ++mt) {
                LDMATRIX_X4(ahi[mt][0], ahi[mt][1], ahi[mt][2], ahi[mt][3],
                            QHI + aoff[ks] + (uint32_t)(mt * 2048));
                LDMATRIX_X4(alo[mt][0], alo[mt][1], alo[mt][2], alo[mt][3],
                            QLO + aoff[ks] + (uint32_t)(mt * 2048));
            }
            uint32_t bhi[2][2], blo[2][2];
            {
                uint32_t r0, r1, r2, r3;
                LDMATRIX_X4(r0, r1, r2, r3, KHt + boff[ks] + 2048u);
                bhi[0][0] = r0; bhi[0][1] = r1; bhi[1][0] = r2; bhi[1][1] = r3;
                LDMATRIX_X4(r0, r1, r2, r3, KLt + boff[ks] + 2048u);
                blo[0][0] = r0; blo[0][1] = r1; blo[1][0] = r2; blo[1][1] = r3;
            }
#pragma unroll
            for (int mt = 0; mt < 4; ++mt)
#pragma unroll
                for (int nt = 0; nt < 2; ++nt) {
                    MMA_16816(acc1[mt][nt], ahi[mt], bhi[nt]);
                    MMA_16816(acc1[mt][nt], alo[mt], bhi[nt]);
                    MMA_16816(acc1[mt][nt], ahi[mt], blo[nt]);
                }
            EPI_CHUNK(acc0, ks, colt, 0);
        }
        pcolt = colt;
    }

    // ---- drain: epilogue of the last tile's acc1 (the only exposed chunk).
#pragma unroll
    for (int mt = 0; mt < 4; ++mt)
        EPI_CHUNK(acc1, mt, pcolt, 16);
}

// ---------------------------------------------------------------------------
extern "C" void kernel_launch(void* const* d_in, const int* in_sizes, int n_in,
                              void* d_out, int out_size) {
    const float* q = (const float*)d_in[0];
    const float* k = (const float*)d_in[1];
    float* out = (float*)d_out;

    cudaFuncSetAttribute(hept_mma_kernel,
                         cudaFuncAttributeMaxDynamicSharedMemorySize, SM_ALLOC);

    dim3 pgrid(HEADS * NSEQ / 16, 2, 1);
    hept_prep_kernel<<<pgrid, 256>>>(q, k);

    dim3 mgrid(NSEQ / (TILE * KTILES), NSEQ / TILE, HEADS);
    hept_mma_kernel<<<mgrid, 256, SM_ALLOC>>>(out);
}

// round 14
// speedup vs baseline: 1.1168x; 1.1168x over previous
#include <cuda_runtime.h>
#include <cuda_fp16.h>
#include <cstdint>

// Shape fixed by setup_inputs: B=1, H=8, N=4096, D=64, fp32 in/out.
#define HEADS 8
#define NSEQ  4096
#define DDIM  64
#define TILE  128
#define KTILES 2            // two 128-col K tiles resident -> 128x256 per CTA

// SW128 swizzle (Swizzle<3,4,3>) on byte offsets relative to a 1024B-aligned base.
#define SW128(off) ((off) ^ ((((uint32_t)(off)) >> 3) & 0x70))

// Pre-scaled norms: g_q2[r] = -0.5*log2(e)*||q_r||^2 (same for k).
__device__ float g_q2[HEADS * NSEQ];
__device__ float g_k2[HEADS * NSEQ];
// fp16 hi/lo split of Q and K, same [h, row, d] layout (4 MB each).
__device__ __half g_qhi[HEADS * NSEQ * DDIM];
__device__ __half g_qlo[HEADS * NSEQ * DDIM];
__device__ __half g_khi[HEADS * NSEQ * DDIM];
__device__ __half g_klo[HEADS * NSEQ * DDIM];

// ---------------------------------------------------------------------------
// Kernel 1: fused (pre-scaled) norms + fp16 hi/lo split, single input pass.
// ---------------------------------------------------------------------------
__global__ void hept_prep_kernel(const float* __restrict__ q,
                                 const float* __restrict__ k) {
    const int tid = threadIdx.x;
    const int rloc = tid >> 4;
    const int c4   = tid & 15;
    const int row  = blockIdx.x * 16 + rloc;
    const float* src = (blockIdx.y == 0) ? q : k;
    float*       nrm = (blockIdx.y == 0) ? g_q2 : g_k2;
    __half* hi = (blockIdx.y == 0) ? g_qhi : g_khi;
    __half* lo = (blockIdx.y == 0) ? g_qlo : g_klo;

    float4 v = reinterpret_cast<const float4*>(src)[row * 16 + c4];

    __half2 h01 = __floats2half2_rn(v.x, v.y);
    __half2 h23 = __floats2half2_rn(v.z, v.w);
    float2 f01 = __half22float2(h01);
    float2 f23 = __half22float2(h23);
    __half2 l01 = __floats2half2_rn(v.x - f01.x, v.y - f01.y);
    __half2 l23 = __floats2half2_rn(v.z - f23.x, v.w - f23.y);
    reinterpret_cast<uint2*>(hi)[row * 16 + c4] =
        make_uint2(*reinterpret_cast<uint32_t*>(&h01), *reinterpret_cast<uint32_t*>(&h23));
    reinterpret_cast<uint2*>(lo)[row * 16 + c4] =
        make_uint2(*reinterpret_cast<uint32_t*>(&l01), *reinterpret_cast<uint32_t*>(&l23));

    float s = v.x * v.x + v.y * v.y + v.z * v.z + v.w * v.w;
#pragma unroll
    for (int off = 8; off >= 1; off >>= 1)
        s += __shfl_xor_sync(0xffffffffu, s, off);
    if (c4 == 0) nrm[row] = s * -0.72134752044448170368f;   // -0.5*log2(e)
}

// ---------------------------------------------------------------------------
static __device__ __forceinline__ uint32_t smem_u32(const void* p) {
    uint32_t a;
    asm("{ .reg .u64 t; cvta.to.shared.u64 t, %1; cvt.u32.u64 %0, t; }"
        : "=r"(a) : "l"(p));
    return a;
}

static __device__ __forceinline__ float ex2(float x) {
    float y;
    asm("ex2.approx.f32 %0, %1;" : "=f"(y) : "f"(x));
    return y;
}

#define CP_ASYNC16(dst, src)                                                  \
    asm volatile("cp.async.cg.shared.global [%0], [%1], 16;"                  \
                 :: "r"(dst), "l"(src) : "memory")

#define LDMATRIX_X4(r0, r1, r2, r3, addr)                                     \
    asm volatile("ldmatrix.sync.aligned.m8n8.x4.shared.b16 {%0,%1,%2,%3}, [%4];" \
                 : "=r"(r0), "=r"(r1), "=r"(r2), "=r"(r3) : "r"(addr))

#define MMA_16816(c, a, b)                                                     \
    asm volatile("mma.sync.aligned.m16n8k16.row.col.f32.f16.f16.f32 "         \
                 "{%0,%1,%2,%3}, {%4,%5,%6,%7}, {%8,%9}, {%0,%1,%2,%3};"      \
                 : "+f"((c)[0]), "+f"((c)[1]), "+f"((c)[2]), "+f"((c)[3])     \
                 : "r"((a)[0]), "r"((a)[1]), "r"((a)[2]), "r"((a)[3]),        \
                   "r"((b)[0]), "r"((b)[1]))

// ---------------------------------------------------------------------------
// Kernel 2: HMMA fp16-split GEMM + log2-exp epilogue (R11 structure).
// ANTI-PHASE: odd warps process the two resident K tiles in reverse order,
// so one warp parity is always in its MMA phase while the other is in its
// epilogue phase -> tensor pipe stays fed without extra registers/LDSM.
// Grid (16, 32, 8), 256 threads (8 warps, 2m x 4n), warp tile 64x32.
// dyn smem: QHI|QLO (16KB each) | KHI(32KB, 256 rows) | KLO(32KB) = 96KB.
// ---------------------------------------------------------------------------
#define SM_QB   16384
#define SM_KB   32768
#define SM_ALLOC (2 * SM_QB + 2 * SM_KB + 1024)

__global__ __launch_bounds__(256, 2)
void hept_mma_kernel(float* __restrict__ out) {
    extern __shared__ char smem_raw[];
    const uint32_t sbase = smem_u32(smem_raw);
    const uint32_t abase = (sbase + 1023u) & ~1023u;

    const uint32_t QHI = abase;
    const uint32_t QLO = abase + SM_QB;
    const uint32_t KHI = abase + 2 * SM_QB;
    const uint32_t KLO = abase + 2 * SM_QB + SM_KB;

    const int tid  = threadIdx.x;
    const int lane = tid & 31;
    const int wid  = tid >> 5;
    const int wm   = wid >> 2;          // 0..1 -> 64-row slab
    const int wn   = wid & 3;           // 0..3 -> 32-col slab
    const int h    = blockIdx.z;
    const int row0 = blockIdx.y * TILE;
    const int col0 = blockIdx.x * (TILE * KTILES);

    const __half* qhis = g_qhi + ((size_t)h * NSEQ + row0) * DDIM;
    const __half* qlos = g_qlo + ((size_t)h * NSEQ + row0) * DDIM;
    const __half* khis = g_khi + ((size_t)h * NSEQ + col0) * DDIM;
    const __half* klos = g_klo + ((size_t)h * NSEQ + col0) * DDIM;

    // --- single load phase: Q 128 rows, K 256 rows (hi+lo each), 16B chunks.
#pragma unroll
    for (int it = 0; it < 4; ++it) {
        int idx = tid + it * 256;
        int r   = idx >> 3;
        int c16 = idx & 7;
        uint32_t soff = SW128((uint32_t)(r * 128 + c16 * 16));
        size_t goff = (size_t)r * DDIM + c16 * 8;
        CP_ASYNC16(QHI + soff, qhis + goff);
        CP_ASYNC16(QLO + soff, qlos + goff);
    }
#pragma unroll
    for (int it = 0; it < 8; ++it) {
        int idx = tid + it * 256;
        int r   = idx >> 3;                  // 0..255
        int c16 = idx & 7;
        uint32_t soff = SW128((uint32_t)(r * 128 + c16 * 16));
        size_t goff = (size_t)r * DDIM + c16 * 8;
        CP_ASYNC16(KHI + soff, khis + goff);
        CP_ASYNC16(KLO + soff, klos + goff);
    }
    asm volatile("cp.async.commit_group;" ::: "memory");
    asm volatile("cp.async.wait_group 0;" ::: "memory");
    __syncthreads();

    // --- hoisted swizzled LDSM offsets.
    const uint32_t mask = (uint32_t)((lane & 7) << 4);
    const uint32_t a_row = (uint32_t)(wm * 64 + (lane & 7) + ((lane >> 3) & 1) * 8);
    const uint32_t a_colb = (uint32_t)(((lane >> 4) & 1) * 16);
    const uint32_t b_row = (uint32_t)(wn * 32 + (lane & 7) + ((lane >> 4) & 1) * 8);
    const uint32_t b_colb = (uint32_t)(((lane >> 3) & 1) * 16);

    uint32_t aoff[4], boff[4];
#pragma unroll
    for (int ks = 0; ks < 4; ++ks) {
        aoff[ks] = a_row * 128 + ((a_colb + (uint32_t)(ks * 32)) ^ mask);
        boff[ks] = b_row * 128 + ((b_colb + (uint32_t)(ks * 32)) ^ mask);
    }

    const float L2E = 1.4426950408889634f;
    const float* q2p = g_q2 + h * NSEQ + row0;
    float* outh = out + (size_t)h * NSEQ * NSEQ;

    const int worder = wid & 1;          // odd warps reverse tile order

#pragma unroll
    for (int tt = 0; tt < KTILES; ++tt) {
        const int t = tt ^ worder;
        const uint32_t KHt = KHI + (uint32_t)t * (TILE * 128);
        const uint32_t KLt = KLO + (uint32_t)t * (TILE * 128);

        float acc[4][4][4];
#pragma unroll
        for (int mt = 0; mt < 4; ++mt)
#pragma unroll
            for (int nt = 0; nt < 4; ++nt)
#pragma unroll
                for (int i = 0; i < 4; ++i) acc[mt][nt][i] = 0.f;

#pragma unroll
        for (int ks = 0; ks < 4; ++ks) {
            uint32_t ahi[4][4], alo[4][4];
#pragma unroll
            for (int mt = 0; mt < 4; ++mt) {
                LDMATRIX_X4(ahi[mt][0], ahi[mt][1], ahi[mt][2], ahi[mt][3],
                            QHI + aoff[ks] + (uint32_t)(mt * 2048));
                LDMATRIX_X4(alo[mt][0], alo[mt][1], alo[mt][2], alo[mt][3],
                            QLO + aoff[ks] + (uint32_t)(mt * 2048));
            }
            uint32_t bhi[4][2], blo[4][2];
            {
                uint32_t r0, r1, r2, r3;
                LDMATRIX_X4(r0, r1, r2, r3, KHt + boff[ks]);
                bhi[0][0] = r0; bhi[0][1] = r1; bhi[1][0] = r2; bhi[1][1] = r3;
                LDMATRIX_X4(r0, r1, r2, r3, KLt + boff[ks]);
                blo[0][0] = r0; blo[0][1] = r1; blo[1][0] = r2; blo[1][1] = r3;
                LDMATRIX_X4(r0, r1, r2, r3, KHt + boff[ks] + 2048u);
                bhi[2][0] = r0; bhi[2][1] = r1; bhi[3][0] = r2; bhi[3][1] = r3;
                LDMATRIX_X4(r0, r1, r2, r3, KLt + boff[ks] + 2048u);
                blo[2][0] = r0; blo[2][1] = r1; blo[3][0] = r2; blo[3][1] = r3;
            }
            // 48 MMAs: hi*hi + lo*hi + hi*lo (lo*lo dropped, ~2^-22).
#pragma unroll
            for (int mt = 0; mt < 4; ++mt)
#pragma unroll
                for (int nt = 0; nt < 4; ++nt)
                    MMA_16816(acc[mt][nt], ahi[mt], bhi[nt]);
#pragma unroll
            for (int mt = 0; mt < 4; ++mt)
#pragma unroll
                for (int nt = 0; nt < 4; ++nt)
                    MMA_16816(acc[mt][nt], alo[mt], bhi[nt]);
#pragma unroll
            for (int mt = 0; mt < 4; ++mt)
#pragma unroll
                for (int nt = 0; nt < 4; ++nt)
                    MMA_16816(acc[mt][nt], ahi[mt], blo[nt]);
        }

        // --- epilogue (log2 domain): out = exp2(min(log2e*qk + cq + ck, 0)).
        const int colt = col0 + t * TILE;
        const float* k2p = g_k2 + h * NSEQ + colt;
#pragma unroll
        for (int mt = 0; mt < 4; ++mt) {
            const int rA = wm * 64 + mt * 16 + (lane >> 2);
            const int rB = rA + 8;
            const float cqA = q2p[rA];
            const float cqB = q2p[rB];
            float* orowA = outh + (size_t)(row0 + rA) * NSEQ + colt;
            float* orowB = outh + (size_t)(row0 + rB) * NSEQ + colt;
#pragma unroll
            for (int nt = 0; nt < 4; ++nt) {
                const int c = wn * 32 + nt * 8 + (lane & 3) * 2;
                const float ckA = k2p[c];
                const float ckB = k2p[c + 1];
                const float* v = acc[mt][nt];
                float2 oA, oB;
                oA.x = ex2(fminf(fmaf(v[0], L2E, cqA + ckA), 0.f));
                oA.y = ex2(fminf(fmaf(v[1], L2E, cqA + ckB), 0.f));
                oB.x = ex2(fminf(fmaf(v[2], L2E, cqB + ckA), 0.f));
                oB.y = ex2(fminf(fmaf(v[3], L2E, cqB + ckB), 0.f));
                *reinterpret_cast<float2*>(orowA + c) = oA;
                *reinterpret_cast<float2*>(orowB + c) = oB;
            }
        }
        // no barrier: warps flow directly into the next tile's MMA
    }
}

// ---------------------------------------------------------------------------
extern "C" void kernel_launch(void* const* d_in, const int* in_sizes, int n_in,
                              void* d_out, int out_size) {
    const float* q = (const float*)d_in[0];
    const float* k = (const float*)d_in[1];
    float* out = (float*)d_out;

    cudaFuncSetAttribute(hept_mma_kernel,
                         cudaFuncAttributeMaxDynamicSharedMemorySize, SM_ALLOC);

    dim3 pgrid(HEADS * NSEQ / 16, 2, 1);
    hept_prep_kernel<<<pgrid, 256>>>(q, k);

    dim3 mgrid(NSEQ / (TILE * KTILES), NSEQ / TILE, HEADS);
    hept_mma_kernel<<<mgrid, 256, SM_ALLOC>>>(out);
}